// round 13
// baseline (speedup 1.0000x reference)
#include <cuda_runtime.h>

#define Bb 2
#define Nn 8192
#define Ff 64
#define Oo 64
#define GRID 64
#define GPB  32          // blocks per batch (barrier group size)
#define TPB 512
#define NWARP 16
#define RPB 256          // rows per block
#define NGRP 32          // row groups (TPB/16)
#define ITERS 8          // RPB / NGRP

// Epoch-parity double-buffered accumulators: launch with epoch E uses slot E&1
// (zeroed by the previous launch / static init); lead block zeroes slot (E&1)^1
// at start for the NEXT launch.
__device__ __align__(16) float g_Sj[2][Bb];
__device__ __align__(16) float g_Pa[2][Bb * Oo];
__device__ __align__(16) float g_Qa[2][Bb * Oo];
__device__ unsigned long long g_c1[Bb];   // barrier-1 counter: +GPB per launch
__device__ unsigned long long g_c2[Bb];   // barrier-2 counter: +GPB per launch

__device__ __forceinline__ unsigned long long ctr_load_acq(const unsigned long long* p) {
    unsigned long long v;
    asm volatile("ld.acquire.gpu.global.u64 %0, [%1];" : "=l"(v) : "l"(p) : "memory");
    return v;
}
__device__ __forceinline__ unsigned long long ctr_load_cg(const unsigned long long* p) {
    unsigned long long v;
    asm volatile("ld.global.cg.u64 %0, [%1];" : "=l"(v) : "l"(p) : "memory");
    return v;
}
__device__ __forceinline__ void red_add_release_u64(unsigned long long* p) {
    asm volatile("red.release.gpu.global.add.u64 [%0], %1;"
                 :: "l"(p), "l"(1ULL) : "memory");
}
__device__ __forceinline__ float f_load_cg(const float* p) {
    float v;
    asm volatile("ld.global.cg.f32 %0, [%1];" : "=f"(v) : "l"(p) : "memory");
    return v;
}

__global__ void __launch_bounds__(TPB, 1) k_fused(
    const float* __restrict__ x, const float* __restrict__ adj_w,
    const float* __restrict__ adj_b, const float* __restrict__ weight,
    const float* __restrict__ bias, float* __restrict__ out)
{
    __shared__ float s_pu[NGRP * Ff];        // 8 KB
    __shared__ float s_pv[NGRP * Ff];        // 8 KB
    __shared__ float s_u[Ff], s_v[Ff];
    __shared__ float sB[Oo];
    __shared__ float s_W[Ff * Oo];           // 16 KB
    __shared__ float s_wsum[NWARP];

    const int tid  = threadIdx.x;
    const int lane = tid & 15;               // feature quad
    const int grp  = tid >> 4;               // row group (0..31)
    const int wid  = tid >> 5;
    const int bid  = blockIdx.x;
    const int bb   = bid >> 5;               // batch (32 blocks/batch)
    const int row0 = bid * RPB;

    // g_c2 only advances during barrier 2 of THIS launch (after barrier 1 has
    // fully completed), and launches are stream-serialized, so the entry read
    // is race-free and an exact multiple of GPB. Both targets and the parity
    // derive from it — no atomic-with-return needed anywhere.
    const unsigned long long c2e = ctr_load_cg(&g_c2[bb]);
    const unsigned long long epoch = c2e / GPB;
    const int par = (int)(epoch & 1ULL);
    const unsigned long long t1 = epoch * GPB + GPB;   // g_c1 target
    const unsigned long long t2 = c2e + GPB;           // g_c2 target

    // ---------------- x loads FIRST (critical DRAM path) ----------------------
    float4 xv[ITERS];
    #pragma unroll
    for (int it = 0; it < ITERS; ++it)
        xv[it] = reinterpret_cast<const float4*>(x)[(row0 + it * NGRP + grp) * 16 + lane];

    const float c = adj_b[0];
    const float4 wj = reinterpret_cast<const float4*>(adj_w)[lane];
    const float4 wi = reinterpret_cast<const float4*>(adj_w)[16 + lane];

    // Stage weight + bias behind the x loads (2x float4 per thread).
    #pragma unroll
    for (int k = 0; k < 2; ++k)
        reinterpret_cast<float4*>(s_W)[k * TPB + tid] =
            reinterpret_cast<const float4*>(weight)[k * TPB + tid];
    if (tid < Oo) sB[tid] = bias[tid];

    // Lead block per batch zeroes the NEXT launch's slots (off critical path).
    if ((bid & 31) == 0) {
        if (tid < Oo)            g_Pa[par ^ 1][bb * Oo + tid] = 0.0f;
        else if (tid < 2 * Oo)   g_Qa[par ^ 1][bb * Oo + tid - Oo] = 0.0f;
        else if (tid == 2 * Oo)  g_Sj[par ^ 1][bb] = 0.0f;
    }

    // ---------------- Phase 1a: lane-partial sj sums only --------------------
    float pjp[ITERS];
    float bl = 0.0f;                         // per-lane partial of block Sj
    #pragma unroll
    for (int it = 0; it < ITERS; ++it) {
        pjp[it] = xv[it].x * wj.x + xv[it].y * wj.y + xv[it].z * wj.z + xv[it].w * wj.w;
        bl += pjp[it];
    }
    #pragma unroll
    for (int off = 16; off; off >>= 1)       // one warp fold, not per-row folds
        bl += __shfl_xor_sync(0xffffffffu, bl, off);
    if ((tid & 31) == 0) s_wsum[wid] = bl;
    __syncthreads();

    // ---------------- Barrier 1 ARRIVE (RED, no return) -----------------------
    if (tid == 0) {
        float s = 0.f;
        #pragma unroll
        for (int w = 0; w < NWARP; ++w) s += s_wsum[w];
        atomicAdd(&g_Sj[par][bb], s);
        __threadfence();
        red_add_release_u64(&g_c1[bb]);      // fire-and-forget arrival
    }

    // ---------------- Phase 1b: per-row folds (hidden under barrier wait) ----
    float rsj[ITERS], rsi[ITERS];
    #pragma unroll
    for (int it = 0; it < ITERS; ++it) {
        float pj = pjp[it];
        #pragma unroll
        for (int off = 8; off; off >>= 1)
            pj += __shfl_xor_sync(0xffffffffu, pj, off, 16);
        rsj[it] = pj;
    }
    #pragma unroll
    for (int it = 0; it < ITERS; ++it) {
        float pi = xv[it].x * wi.x + xv[it].y * wi.y + xv[it].z * wi.z + xv[it].w * wi.w;
        #pragma unroll
        for (int off = 8; off; off >>= 1)
            pi += __shfl_xor_sync(0xffffffffu, pi, off, 16);
        rsi[it] = pi;
    }

    // ---------------- Barrier 1 WAIT (acquire poll) ---------------------------
    if (tid == 0) {
        while (ctr_load_acq(&g_c1[bb]) < t1) __nanosleep(20);
    }
    __syncthreads();

    const float Sj = f_load_cg(&g_Sj[par][bb]);   // single L2 load

    // ---------------- Phase 2: u/v block partials -----------------------------
    float4 au = make_float4(0.f, 0.f, 0.f, 0.f);
    float4 av = make_float4(0.f, 0.f, 0.f, 0.f);
    float rd[ITERS], ra[ITERS];
    #pragma unroll
    for (int it = 0; it < ITERS; ++it) {
        float d  = rsqrtf(fmaxf((float)Nn * (rsi[it] + c) + Sj, 1.0f));
        rd[it] = d;
        ra[it] = rsi[it] + c;
        float sd = rsj[it] * d;
        au.x += d  * xv[it].x;  au.y += d  * xv[it].y;
        au.z += d  * xv[it].z;  au.w += d  * xv[it].w;
        av.x += sd * xv[it].x;  av.y += sd * xv[it].y;
        av.z += sd * xv[it].z;  av.w += sd * xv[it].w;
    }
    reinterpret_cast<float4*>(s_pu)[grp * 16 + lane] = au;
    reinterpret_cast<float4*>(s_pv)[grp * 16 + lane] = av;
    __syncthreads();
    if (tid < 64) {
        float a = 0.f;
        #pragma unroll
        for (int g = 0; g < NGRP; ++g) a += s_pu[g * Ff + tid];
        s_u[tid] = a;
    } else if (tid < 128) {
        int f = tid - 64;
        float a = 0.f;
        #pragma unroll
        for (int g = 0; g < NGRP; ++g) a += s_pv[g * Ff + f];
        s_v[f] = a;
    }
    __syncthreads();

    // ---------------- Local micro-GEMM + RED of P,Q (P linear in u) ----------
    if (tid < 64) {
        float p0 = 0.f, p1 = 0.f;
        #pragma unroll
        for (int f = 0; f < 32; ++f) {
            p0 = fmaf(s_u[f],      s_W[f * Oo + tid],        p0);
            p1 = fmaf(s_u[f + 32], s_W[(f + 32) * Oo + tid], p1);
        }
        atomicAdd(&g_Pa[par][bb * Oo + tid], p0 + p1);
    } else if (tid < 128) {
        int o = tid - 64;
        float q0 = 0.f, q1 = 0.f;
        #pragma unroll
        for (int f = 0; f < 32; ++f) {
            q0 = fmaf(s_v[f],      s_W[f * Oo + o],        q0);
            q1 = fmaf(s_v[f + 32], s_W[(f + 32) * Oo + o], q1);
        }
        atomicAdd(&g_Qa[par][bb * Oo + o], q0 + q1);
    }
    __syncthreads();

    // ---------------- Barrier 2 (RED arrival, single release fence) -----------
    if (tid == 0) {
        __threadfence();                      // publish this block's P/Q REDs
        red_add_release_u64(&g_c2[bb]);       // fire-and-forget arrival
        while (ctr_load_acq(&g_c2[bb]) < t2) __nanosleep(20);
    }
    __syncthreads();

    // ---------------- Phase 4: rank-1 epilogue (direct P/Q loads) -------------
    const int o4 = lane * 4;
    const float4 Pv = __ldcg(reinterpret_cast<const float4*>(&g_Pa[par][bb * Oo + o4]));
    const float4 Qv = __ldcg(reinterpret_cast<const float4*>(&g_Qa[par][bb * Oo + o4]));
    const float B0 = sB[o4 + 0], B1 = sB[o4 + 1], B2 = sB[o4 + 2], B3 = sB[o4 + 3];
    #pragma unroll
    for (int it = 0; it < ITERS; ++it) {
        const float d = rd[it];
        const float a = ra[it];
        float4 r;
        r.x = fmaxf(fmaf(d, fmaf(a, Pv.x, Qv.x), B0), 0.0f);
        r.y = fmaxf(fmaf(d, fmaf(a, Pv.y, Qv.y), B1), 0.0f);
        r.z = fmaxf(fmaf(d, fmaf(a, Pv.z, Qv.z), B2), 0.0f);
        r.w = fmaxf(fmaf(d, fmaf(a, Pv.w, Qv.w), B3), 0.0f);
        reinterpret_cast<float4*>(out)[(row0 + it * NGRP + grp) * 16 + lane] = r;
    }
}

extern "C" void kernel_launch(void* const* d_in, const int* in_sizes, int n_in,
                              void* d_out, int out_size) {
    const float* x      = (const float*)d_in[0];
    const float* adj_w  = (const float*)d_in[1];
    const float* adj_b  = (const float*)d_in[2];
    const float* weight = (const float*)d_in[3];
    const float* bias   = (const float*)d_in[4];
    float* out = (float*)d_out;

    k_fused<<<GRID, TPB>>>(x, adj_w, adj_b, weight, bias, out);
}